// round 8
// baseline (speedup 1.0000x reference)
#include <cuda_runtime.h>

#define NXc 64
#define NYc 64
#define NSPOTS 64
#define Pc 6
#define TPB 256          // 8 warps; warp w owns image rows [8w, 8w+8) = tile row w

__global__ __launch_bounds__(TPB) void spot_render_kernel(
    const float* __restrict__ z, float* __restrict__ out)
{
    __shared__ float slx[NSPOTS * Pc];   // 500 * dx * valid   (I0*0.5 folded)
    __shared__ float sly[NSPOTS * Pc];   // 0.5 * dy * valid
    __shared__ int   spxy[NSPOTS];       // r0 | c0<<8  (r0=255 sentinel if invalid)
    __shared__ float sx0p[NSPOTS];
    __shared__ float sy0p[NSPOTS];
    __shared__ float sval[NSPOTS];

    const int b    = blockIdx.x;
    const int tid  = threadIdx.x;
    const int lane = tid & 31;
    const int w    = tid >> 5;
    const int band_lo = w << 3;

    const float inv_alpha = 1.0f / (1.41421356237f * 0.92f);

    // ---- meta: one thread per spot ----
    if (tid < NSPOTS) {
        const int s = tid;
        const float* zrow = z + (size_t)b * (2 * NSPOTS);
        const float x0 = __ldg(zrow + s);
        const float y0 = __ldg(zrow + NSPOTS + s);
        const int px = __float2int_rn(x0) - 3;          // round-half-even == jnp.round
        const int py = __float2int_rn(y0) - 3;
        const bool valid = (px >= 0) & (px < NXc - Pc) & (py >= 0) & (py < NYc - Pc);
        spxy[s] = (valid ? px : 255) | ((valid ? py : 0) << 8);  // 255 -> no tile
        sx0p[s] = x0 - (float)px;
        sy0p[s] = y0 - (float)py;
        sval[s] = valid ? 1.0f : 0.0f;
    }
    __syncthreads();

    // ---- per-warp tile masks via ballot (registers only, no syncs) ----
    unsigned mlo[8], mhi[8];
    {
        const int meta1 = spxy[lane];
        const int r01 = meta1 & 255, c01 = meta1 >> 8;
        const bool rov1 = (r01 + Pc > band_lo) && (r01 < band_lo + 8);
        const int tl1 = c01 >> 3, th1 = (c01 + 5) >> 3;
        const int meta2 = spxy[lane + 32];
        const int r02 = meta2 & 255, c02 = meta2 >> 8;
        const bool rov2 = (r02 + Pc > band_lo) && (r02 < band_lo + 8);
        const int tl2 = c02 >> 3, th2 = (c02 + 5) >> 3;
        #pragma unroll
        for (int tx = 0; tx < 8; tx++) {
            mlo[tx] = __ballot_sync(0xFFFFFFFFu, rov1 & (tx >= tl1) & (tx <= th1));
            mhi[tx] = __ballot_sync(0xFFFFFFFFu, rov2 & (tx >= tl2) & (tx <= th2));
        }
    }

    // ---- erf phase: 128 items x 2 halves over 256 threads (4 erfs each) ----
    // item (s,d), half h: h=0 -> j=0..3 (diffs 0..2), h=1 -> j=3..6 (diffs 3..5)
    {
        const int it = tid & 127;
        const int h  = tid >> 7;
        const int s  = it & 63;
        const int d  = it >> 6;                 // 0 = x, 1 = y
        const float t0 = d ? sy0p[s] : sx0p[s];
        const float scale = (d ? 0.5f : 500.0f) * sval[s];
        const int jb = h * 3;
        const float e0 = erff(((float)(jb + 0) - 0.5f - t0) * inv_alpha);
        const float e1 = erff(((float)(jb + 1) - 0.5f - t0) * inv_alpha);
        const float e2 = erff(((float)(jb + 2) - 0.5f - t0) * inv_alpha);
        const float e3 = erff(((float)(jb + 3) - 0.5f - t0) * inv_alpha);
        float* dst = (d ? sly : slx) + s * Pc + jb;
        dst[0] = (e1 - e0) * scale;
        dst[1] = (e2 - e1) * scale;
        dst[2] = (e3 - e2) * scale;
    }
    __syncthreads();

    // ---- gather: lane owns 2 pixels per tile, 8 tiles, direct STG ----
    const int r     = band_lo + (lane >> 2);    // this lane's image row
    const int cbase = (lane & 3) << 1;          // col offset within tile
    float* obase = out + (size_t)b * (NXc * NYc) + r * NYc;
    #pragma unroll
    for (int tx = 0; tx < 8; tx++) {
        const int c = (tx << 3) + cbase;
        float a0 = 0.0f, a1 = 0.0f;
        unsigned m = mlo[tx];
        while (m) {
            const int s = __ffs(m) - 1; m &= m - 1;      // warp-uniform
            const int meta = spxy[s];
            const int ix = r - (meta & 255);
            const int iy = c - (meta >> 8);
            float lx = 0.f, ly0 = 0.f, ly1 = 0.f;
            if ((unsigned)ix < 6u)       lx  = slx[s * Pc + ix];
            if ((unsigned)iy < 6u)       ly0 = sly[s * Pc + iy];
            if ((unsigned)(iy + 1) < 6u) ly1 = sly[s * Pc + iy + 1];
            a0 = fmaf(lx, ly0, a0);
            a1 = fmaf(lx, ly1, a1);
        }
        unsigned m2 = mhi[tx];
        while (m2) {
            const int s = __ffs(m2) + 31; m2 &= m2 - 1;  // +32-1
            const int meta = spxy[s];
            const int ix = r - (meta & 255);
            const int iy = c - (meta >> 8);
            float lx = 0.f, ly0 = 0.f, ly1 = 0.f;
            if ((unsigned)ix < 6u)       lx  = slx[s * Pc + ix];
            if ((unsigned)iy < 6u)       ly0 = sly[s * Pc + iy];
            if ((unsigned)(iy + 1) < 6u) ly1 = sly[s * Pc + iy + 1];
            a0 = fmaf(lx, ly0, a0);
            a1 = fmaf(lx, ly1, a1);
        }
        *reinterpret_cast<float2*>(obase + c) = make_float2(a0, a1);
    }
}

extern "C" void kernel_launch(void* const* d_in, const int* in_sizes, int n_in,
                              void* d_out, int out_size)
{
    const float* z = (const float*)d_in[0];
    float* out = (float*)d_out;
    const int B = in_sizes[0] / (2 * NSPOTS);   // 8192
    spot_render_kernel<<<B, TPB>>>(z, out);
}

// round 10
// speedup vs baseline: 1.5534x; 1.5534x over previous
#include <cuda_runtime.h>

#define NXc 64
#define NYc 64
#define NSPOTS 64
#define Pc 6
#define TPB 256

#define FIXS   65536.0f          // 2^16 fixed-point scale
#define INV_FIXS (1.0f / 65536.0f)

__global__ __launch_bounds__(TPB) void spot_render_kernel(
    const float* __restrict__ z, float* __restrict__ out)
{
    __shared__ unsigned long long img64[NXc * (NYc / 2)];  // 16 KB, rotate-4r swizzled cells
    __shared__ float slx[NSPOTS * Pc];   // I0 * 0.5 * FIXS * dx * valid
    __shared__ float sly[NSPOTS * Pc];   // 0.5 * dy * valid
    __shared__ int   spxy[NSPOTS];       // clamped px | py<<8
    __shared__ float sx0p[NSPOTS];
    __shared__ float sy0p[NSPOTS];
    __shared__ float sval[NSPOTS];

    const int b    = blockIdx.x;
    const int tid  = threadIdx.x;
    const int lane = tid & 31;
    const int w    = tid >> 5;

    const float inv_alpha = 1.0f / (1.41421356237f * 0.92f);

    // ---- meta: one thread per spot ----
    if (tid < NSPOTS) {
        const int s = tid;
        const float* zrow = z + (size_t)b * (2 * NSPOTS);
        const float x0 = __ldg(zrow + s);
        const float y0 = __ldg(zrow + NSPOTS + s);
        const int px = __float2int_rn(x0) - 3;          // round-half-even == jnp.round
        const int py = __float2int_rn(y0) - 3;
        const bool valid = (px >= 0) & (px < NXc - Pc) & (py >= 0) & (py < NYc - Pc);
        spxy[s] = (valid ? px : 0) | ((valid ? py : 0) << 8);
        sx0p[s] = x0 - (float)px;
        sy0p[s] = y0 - (float)py;
        sval[s] = valid ? 1.0f : 0.0f;
    }
    __syncthreads();

    // ---- warps 0-3: dedup'd erf (7 per spot-dim) | warps 4-7: zero image ----
    if (tid < 128) {
        const int s = tid & 63;
        const int d = tid >> 6;                          // 0 = x, 1 = y
        const float t0 = d ? sy0p[s] : sx0p[s];
        // fold the two 0.5 factors: x gets 1000*0.5*FIXS, y gets 0.5
        const float scale = (d ? 0.5f : 500.0f * FIXS) * sval[s];
        float e[7];
        #pragma unroll
        for (int j = 0; j < 7; j++)
            e[j] = erff(((float)j - 0.5f - t0) * inv_alpha);
        float* dst = (d ? sly : slx) + s * Pc;
        #pragma unroll
        for (int j = 0; j < 6; j++)
            dst[j] = (e[j + 1] - e[j]) * scale;
    } else {
        uint4* im4 = reinterpret_cast<uint4*>(img64);    // 1024 uint4
        const int i = tid - 128;
        const uint4 zz = make_uint4(0u, 0u, 0u, 0u);
        #pragma unroll
        for (int k = 0; k < 8; k++)
            im4[k * 128 + i] = zz;
    }
    __syncthreads();

    // ---- phase C: packed 64-bit fixed-point scatter ----
    // lane (row, j): row = lane>>2 in 0..5, jc = lane&3 cell index; lanes 24-31 idle
    const int row = lane >> 2;
    const int jc  = lane & 3;
    const bool active = (lane < 24);
    #pragma unroll
    for (int k = 0; k < 8; k++) {
        const int s    = w * 8 + k;
        const int meta = spxy[s];                // broadcast
        const int r0   = meta & 255;
        const int c0   = meta >> 8;
        if (active) {
            const int cp  = (c0 >> 1) + jc;      // cell column (pixels 2cp, 2cp+1)
            const int iye = (cp << 1) - c0;      // -1..7
            const int r   = r0 + row;
            const float lx = slx[s * Pc + row];  // 4-lane multicast
            const float ve = ((unsigned)iye       < 6u) ? lx * sly[s * Pc + iye]     : 0.0f;
            const float vo = ((unsigned)(iye + 1) < 6u) ? lx * sly[s * Pc + iye + 1] : 0.0f;
            const unsigned long long pack =
                (unsigned long long)__float2uint_rn(ve) |
                ((unsigned long long)__float2uint_rn(vo) << 32);
            if (pack)                            // skips zero cells AND invalid spots
                atomicAdd(&img64[(r << 5) + ((cp + (r << 2)) & 31)], pack);
        }
    }
    __syncthreads();

    // ---- phase D: unpack + un-swizzle + coalesced float2 writeback ----
    float2* o2 = reinterpret_cast<float2*>(out + (size_t)b * (NXc * NYc));
    #pragma unroll
    for (int k = 0; k < 8; k++) {
        const int i  = k * TPB + tid;            // cell index 0..2047
        const int r  = i >> 5;                   // warp-uniform
        const int cp = i & 31;
        const unsigned long long v = img64[(r << 5) + ((cp + (r << 2)) & 31)];
        const float lo = __uint2float_rn((unsigned)v)         * INV_FIXS;
        const float hi = __uint2float_rn((unsigned)(v >> 32)) * INV_FIXS;
        o2[i] = make_float2(lo, hi);
    }
}

extern "C" void kernel_launch(void* const* d_in, const int* in_sizes, int n_in,
                              void* d_out, int out_size)
{
    const float* z = (const float*)d_in[0];
    float* out = (float*)d_out;
    const int B = in_sizes[0] / (2 * NSPOTS);   // 8192
    spot_render_kernel<<<B, TPB>>>(z, out);
}

// round 11
// speedup vs baseline: 1.8352x; 1.1814x over previous
#include <cuda_runtime.h>

#define NXc 64
#define NYc 64
#define NSPOTS 64
#define Pc 6
#define TPB 256

__global__ __launch_bounds__(TPB) void spot_render_kernel(
    const float* __restrict__ z, float* __restrict__ out)
{
    __shared__ float img[NXc * NYc];     // 16 KB, rotate-6 swizzled rows
    __shared__ float slx[NSPOTS * Pc];   // 500 * dx * valid
    __shared__ float sly[NSPOTS * Pc];   // 0.5 * dy * valid
    __shared__ int   smeta[NSPOTS];      // r0 | K<<6 | valid<<12

    const int b    = blockIdx.x;
    const int tid  = threadIdx.x;
    const int lane = tid & 31;
    const int w    = tid >> 5;

    const float inv_alpha = 1.0f / (1.41421356237f * 0.92f);

    // ---- single prologue region, ONE sync ----
    // warps 0-3: per-(spot,dim) meta + dedup'd erf (7 evals -> 6 lambdas)
    // warps 4-7: zero the 16 KB image
    if (tid < 128) {
        const int s = tid & 63;
        const int d = tid >> 6;                          // 0 = x, 1 = y
        const float* zrow = z + (size_t)b * (2 * NSPOTS);
        const float x0 = __ldg(zrow + s);
        const float y0 = __ldg(zrow + NSPOTS + s);
        const int px = __float2int_rn(x0) - 3;           // round-half-even == jnp.round
        const int py = __float2int_rn(y0) - 3;
        const bool valid = (px >= 0) & (px < NXc - Pc) & (py >= 0) & (py < NYc - Pc);

        if (d == 0) {
            const int r0 = valid ? px : 0;
            const int c0 = valid ? py : 0;
            const int K  = (c0 + 6 * r0) & 63;
            smeta[s] = r0 | (K << 6) | ((int)valid << 12);
        }

        const float t0 = d ? (y0 - (float)py) : (x0 - (float)px);
        const float scale = (d ? 0.5f : 500.0f) * (valid ? 1.0f : 0.0f);
        float e[7];
        #pragma unroll
        for (int j = 0; j < 7; j++)
            e[j] = erff(((float)j - 0.5f - t0) * inv_alpha);
        float* dst = (d ? sly : slx) + s * Pc;
        #pragma unroll
        for (int j = 0; j < 6; j++)
            dst[j] = (e[j + 1] - e[j]) * scale;
    } else {
        float4* im4 = reinterpret_cast<float4*>(img);
        const int i = tid - 128;
        #pragma unroll
        for (int k = 0; k < 8; k++)
            im4[k * 128 + i] = make_float4(0.f, 0.f, 0.f, 0.f);
    }
    __syncthreads();

    // ---- phase C: warp-per-8-spots scatter, conflict-free rotate-6 atomics ----
    // pixel p = 6*ix + iy; addr = (r0+ix)*64 + ((K + p) & 63), K = (c0+6*r0)&63
    // bank = (K + p) mod 32, p distinct per lane -> zero conflicts
    const int p  = lane;
    const int ix = (p * 171) >> 10;          // p/6 for p <= 35
    const int iy = p - ix * Pc;
    #pragma unroll
    for (int k = 0; k < 8; k++) {
        const int s    = w * 8 + k;
        const int meta = smeta[s];           // broadcast
        if (meta >> 12) {                    // warp-uniform: skip invalid spots
            const int r0 = meta & 63;
            const int K  = (meta >> 6) & 63;
            const float v = slx[s * Pc + ix] * sly[s * Pc + iy];
            atomicAdd(&img[((r0 + ix) << 6) + ((K + p) & 63)], v);
        }
    }
    // batched residuals: pixels 32..35 (ix=5, iy=2..5) of all 8 spots in ONE atomic
    {
        const int s2   = w * 8 + (lane >> 2);
        const int p2   = 32 + (lane & 3);
        const int meta = smeta[s2];
        if (meta >> 12) {                    // per-lane predicate
            const int r0 = meta & 63;
            const int K  = (meta >> 6) & 63;
            const float v = slx[s2 * Pc + 5] * sly[s2 * Pc + (p2 - 30)];
            atomicAdd(&img[((r0 + 5) << 6) + ((K + p2) & 63)], v);
        }
    }
    __syncthreads();

    // ---- phase D: un-swizzle + coalesced float2 writeback ----
    float2* o2 = reinterpret_cast<float2*>(out + (size_t)b * (NXc * NYc));
    const float2* im2 = reinterpret_cast<const float2*>(img);
    #pragma unroll
    for (int k = 0; k < 8; k++) {
        const int i  = k * TPB + tid;
        const int r  = i >> 5;               // warp-uniform
        const int cg = i & 31;
        o2[i] = im2[(r << 5) + ((cg + 3 * r) & 31)];
    }
}

extern "C" void kernel_launch(void* const* d_in, const int* in_sizes, int n_in,
                              void* d_out, int out_size)
{
    const float* z = (const float*)d_in[0];
    float* out = (float*)d_out;
    const int B = in_sizes[0] / (2 * NSPOTS);   // 8192
    spot_render_kernel<<<B, TPB>>>(z, out);
}